// round 14
// baseline (speedup 1.0000x reference)
#include <cuda_runtime.h>

#define N_POINTS 65536
#define N_GAUSS  1024
#define GSPLIT   8
#define GCHUNK   (N_GAUSS / GSPLIT)     // 128 gaussians per block chunk (= BLOCK)
#define BLOCK    128
#define PPT      4                      // points per thread
#define PTILE    (BLOCK * PPT)          // 512 points per block
#define NPT      (N_POINTS / PTILE)     // 128 point tiles -> grid 128x8 = 1024 blocks

// Per-gaussian fused params, 12 floats (48 B = 3 x float4), built IN-BLOCK:
// [u00 u01 u02 k0 | u11 u12 k1 u22 | k2 na pad pad]
// M = sqrt(0.5*log2 e)*diag(1/s)*R; Givens-QR M = Q U => q_log2 = |U p + k|^2,
// k = -U c.  contribution = 2^e,  e = na - t0^2 - t1^2 - t2^2,
// na = log2(alpha) - 10   (folds the /1024 mean into the exponent).
__device__ float g_partial[GSPLIT][N_POINTS];
__device__ unsigned g_ticket[NPT];      // monotonic; replay-safe via modulo test

__device__ __forceinline__ float ex2f(float e) {
    float r; asm("ex2.approx.ftz.f32 %0, %1;" : "=f"(r) : "f"(e)); return r;
}

__global__ void __launch_bounds__(BLOCK) eval_kernel(const float* __restrict__ points,
                                                     const float* __restrict__ centers,
                                                     const float* __restrict__ angles,
                                                     const float* __restrict__ scales,
                                                     const float* __restrict__ alphas,
                                                     float* __restrict__ out) {
    __shared__ __align__(16) float4 sg[GCHUNK * 3];   // 6 KB
    __shared__ unsigned s_ticket;

    // ---- load this thread's 4 points first (LDG latency overlaps the QR below) ----
    int base = blockIdx.x * PTILE + threadIdx.x * 2;
    float px[PPT], py[PPT], pz[PPT], acc[PPT];
#pragma unroll
    for (int j = 0; j < PPT / 2; j++) {
        int idx = base + j * (BLOCK * 2);
        const float2* p = reinterpret_cast<const float2*>(points + 3 * idx);
        float2 f0 = p[0], f1 = p[1], f2 = p[2];   // x0 y0 | z0 x1 | y1 z1
        px[2 * j + 0] = f0.x; py[2 * j + 0] = f0.y; pz[2 * j + 0] = f1.x;
        px[2 * j + 1] = f1.y; py[2 * j + 1] = f2.x; pz[2 * j + 1] = f2.y;
        acc[2 * j + 0] = 0.f; acc[2 * j + 1] = 0.f;
    }

    // ---- in-block precompute: every thread QRs one gaussian of this chunk ----
    {
        int m = blockIdx.y * GCHUNK + threadIdx.x;

        float sx, cx, sy, cy, sz, cz;
        sincospif(angles[3 * m + 0], &sx, &cx);     // deg2rad(a*180) = a*pi
        sincospif(angles[3 * m + 1], &sy, &cy);
        sincospif(angles[3 * m + 2], &sz, &cz);

        // R = Rz @ Ry @ Rx
        float r00 = cz * cy;
        float r01 = cz * sy * sx - sz * cx;
        float r02 = cz * sy * cx + sz * sx;
        float r10 = sz * cy;
        float r11 = sz * sy * sx + cz * cx;
        float r12 = sz * sy * cx - cz * sx;
        float r20 = -sy;
        float r21 = cy * sx;
        float r22 = cy * cx;

        const float K = 0.84934163f;   // sqrt(0.5 * log2(e))
        float i0 = K / scales[3 * m + 0];
        float i1 = K / scales[3 * m + 1];
        float i2 = K / scales[3 * m + 2];

        float a0 = r00 * i0, a1 = r01 * i0, a2 = r02 * i0;    // row 0
        float b0 = r10 * i1, b1 = r11 * i1, b2 = r12 * i1;    // row 1
        float g0 = r20 * i2, g1 = r21 * i2, g2 = r22 * i2;    // row 2

        // rot(0,1) zero b0
        {
            float rr = fmaf(a0, a0, b0 * b0);
            float cc = 1.f, ss = 0.f;
            if (rr > 1e-30f) { float inv = rsqrtf(rr); cc = a0 * inv; ss = b0 * inv; }
            float n0 = fmaf(cc, a0, ss * b0);
            float n1 = fmaf(cc, a1, ss * b1);
            float n2 = fmaf(cc, a2, ss * b2);
            float q1 = fmaf(cc, b1, -ss * a1);
            float q2 = fmaf(cc, b2, -ss * a2);
            a0 = n0; a1 = n1; a2 = n2; b1 = q1; b2 = q2;
        }
        // rot(0,2) zero g0
        {
            float rr = fmaf(a0, a0, g0 * g0);
            float cc = 1.f, ss = 0.f;
            if (rr > 1e-30f) { float inv = rsqrtf(rr); cc = a0 * inv; ss = g0 * inv; }
            float n0 = fmaf(cc, a0, ss * g0);
            float n1 = fmaf(cc, a1, ss * g1);
            float n2 = fmaf(cc, a2, ss * g2);
            float q1 = fmaf(cc, g1, -ss * a1);
            float q2 = fmaf(cc, g2, -ss * a2);
            a0 = n0; a1 = n1; a2 = n2; g1 = q1; g2 = q2;
        }
        // rot(1,2) zero g1 (components 1,2 only)
        {
            float rr = fmaf(b1, b1, g1 * g1);
            float cc = 1.f, ss = 0.f;
            if (rr > 1e-30f) { float inv = rsqrtf(rr); cc = b1 * inv; ss = g1 * inv; }
            float n1 = fmaf(cc, b1, ss * g1);
            float n2 = fmaf(cc, b2, ss * g2);
            float q2 = fmaf(cc, g2, -ss * b2);
            b1 = n1; b2 = n2; g2 = q2;
        }
        // U = [a0 a1 a2; 0 b1 b2; 0 0 g2]

        float cx0 = centers[3 * m + 0];
        float cy0 = centers[3 * m + 1];
        float cz0 = centers[3 * m + 2];
        float k0 = -fmaf(a0, cx0, fmaf(a1, cy0, a2 * cz0));
        float k1 = -fmaf(b1, cy0, b2 * cz0);
        float k2 = -(g2 * cz0);
        float na = log2f(alphas[m]) - 10.0f;   // alpha==0 -> -inf -> 2^e = 0 (correct)

        sg[3 * threadIdx.x + 0] = make_float4(a0, a1, a2, k0);
        sg[3 * threadIdx.x + 1] = make_float4(b1, b2, k1, g2);
        sg[3 * threadIdx.x + 2] = make_float4(k2, na, 0.f, 0.f);
    }
    __syncthreads();

    // ---- main loop: 128 gaussians x 4 points, 10 fma-pipe ops + 1 MUFU per point ----
#pragma unroll 2
    for (int m = 0; m < GCHUNK; m++) {
        float4 w0 = sg[3 * m + 0];
        float4 w1 = sg[3 * m + 1];
        float4 w2 = sg[3 * m + 2];
        float u00 = w0.x, u01 = w0.y, u02 = w0.z, k0 = w0.w;
        float u11 = w1.x, u12 = w1.y, k1 = w1.z, u22 = w1.w;
        float k2 = w2.x, na = w2.y;
#pragma unroll
        for (int j = 0; j < PPT; j++) {
            float t0 = fmaf(u00, px[j], fmaf(u01, py[j], fmaf(u02, pz[j], k0)));
            float t1 = fmaf(u11, py[j], fmaf(u12, pz[j], k1));
            float t2 = fmaf(u22, pz[j], k2);
            // e = na - t0^2 - t1^2 - t2^2 : negation folded into FFMA src modifiers
            float e = fmaf(t0, -t0, fmaf(t1, -t1, fmaf(t2, -t2, na)));
            acc[j] += ex2f(e);
        }
    }

    // ---- write this chunk's partial ----
    float* part = g_partial[blockIdx.y];
#pragma unroll
    for (int j = 0; j < PPT / 2; j++) {
        int idx = base + j * (BLOCK * 2);
        *reinterpret_cast<float2*>(part + idx) = make_float2(acc[2 * j + 0], acc[2 * j + 1]);
    }

    // ---- deterministic last-block combine (ticket monotonic -> replay safe) ----
    __threadfence();
    __syncthreads();
    if (threadIdx.x == 0) s_ticket = atomicAdd(&g_ticket[blockIdx.x], 1u);
    __syncthreads();
    if ((s_ticket & (GSPLIT - 1)) == GSPLIT - 1) {
        __threadfence();
#pragma unroll
        for (int j = 0; j < PPT / 2; j++) {
            int idx = base + j * (BLOCK * 2);
            float s0 = 0.f, s1 = 0.f;
#pragma unroll
            for (int g = 0; g < GSPLIT; g++) {      // fixed order -> bitwise deterministic
                const float2* pp = reinterpret_cast<const float2*>(&g_partial[g][idx]);
                float2 v = __ldcg(pp);
                s0 += v.x; s1 += v.y;
            }
            *reinterpret_cast<float2*>(out + idx) = make_float2(s0, s1);
        }
    }
}

extern "C" void kernel_launch(void* const* d_in, const int* in_sizes, int n_in,
                              void* d_out, int out_size) {
    const float* points  = (const float*)d_in[0];
    const float* centers = (const float*)d_in[1];
    const float* angles  = (const float*)d_in[2];
    const float* scales  = (const float*)d_in[3];
    const float* alphas  = (const float*)d_in[4];
    float* out = (float*)d_out;

    dim3 grid(NPT, GSPLIT);
    eval_kernel<<<grid, BLOCK>>>(points, centers, angles, scales, alphas, out);
}

// round 15
// speedup vs baseline: 1.0321x; 1.0321x over previous
#include <cuda_runtime.h>

#define N_POINTS 65536
#define N_GAUSS  1024
#define GSPLIT   16
#define GCHUNK   (N_GAUSS / GSPLIT)     // 64 gaussians per block chunk
#define BLOCK    128
#define PPT      8                      // points per thread
#define PTILE    (BLOCK * PPT)          // 1024 points per block
#define NPT      (N_POINTS / PTILE)     // 64 point tiles -> grid 64x16 = 1024 blocks

// Per-gaussian fused params, 12 floats (48 B = 3 x float4), built IN-BLOCK:
// [u00 u01 u02 k0 | u11 u12 k1 u22 | k2 na pad pad]
// M = sqrt(0.5*log2 e)*diag(1/s)*R; Givens-QR M = Q U => q_log2 = |U p + k|^2,
// k = -U c.  contribution = 2^e,  e = na - t0^2 - t1^2 - t2^2,
// na = log2(alpha) - 10   (folds the /1024 mean into the exponent).
__device__ float g_partial[GSPLIT][N_POINTS];
__device__ unsigned g_ticket[NPT];      // monotonic; replay-safe via modulo test

__device__ __forceinline__ float ex2f(float e) {
    float r; asm("ex2.approx.ftz.f32 %0, %1;" : "=f"(r) : "f"(e)); return r;
}

__global__ void __launch_bounds__(BLOCK) eval_kernel(const float* __restrict__ points,
                                                     const float* __restrict__ centers,
                                                     const float* __restrict__ angles,
                                                     const float* __restrict__ scales,
                                                     const float* __restrict__ alphas,
                                                     float* __restrict__ out) {
    __shared__ __align__(16) float4 sg[GCHUNK * 3];   // 3 KB
    __shared__ unsigned s_ticket;

    // ---- load this thread's 8 points first (LDG latency overlaps the QR below) ----
    int base = blockIdx.x * PTILE + threadIdx.x * 2;
    float px[PPT], py[PPT], pz[PPT], acc[PPT];
#pragma unroll
    for (int j = 0; j < PPT / 2; j++) {
        int idx = base + j * (BLOCK * 2);
        const float2* p = reinterpret_cast<const float2*>(points + 3 * idx);
        float2 f0 = p[0], f1 = p[1], f2 = p[2];   // x0 y0 | z0 x1 | y1 z1
        px[2 * j + 0] = f0.x; py[2 * j + 0] = f0.y; pz[2 * j + 0] = f1.x;
        px[2 * j + 1] = f1.y; py[2 * j + 1] = f2.x; pz[2 * j + 1] = f2.y;
        acc[2 * j + 0] = 0.f; acc[2 * j + 1] = 0.f;
    }

    // ---- in-block precompute: threads 0..63 each QR one gaussian of this chunk ----
    if (threadIdx.x < GCHUNK) {
        int m = blockIdx.y * GCHUNK + threadIdx.x;

        float sx, cx, sy, cy, sz, cz;
        sincospif(angles[3 * m + 0], &sx, &cx);     // deg2rad(a*180) = a*pi
        sincospif(angles[3 * m + 1], &sy, &cy);
        sincospif(angles[3 * m + 2], &sz, &cz);

        // R = Rz @ Ry @ Rx
        float r00 = cz * cy;
        float r01 = cz * sy * sx - sz * cx;
        float r02 = cz * sy * cx + sz * sx;
        float r10 = sz * cy;
        float r11 = sz * sy * sx + cz * cx;
        float r12 = sz * sy * cx - cz * sx;
        float r20 = -sy;
        float r21 = cy * sx;
        float r22 = cy * cx;

        const float K = 0.84934163f;   // sqrt(0.5 * log2(e))
        float i0 = K / scales[3 * m + 0];
        float i1 = K / scales[3 * m + 1];
        float i2 = K / scales[3 * m + 2];

        float a0 = r00 * i0, a1 = r01 * i0, a2 = r02 * i0;    // row 0
        float b0 = r10 * i1, b1 = r11 * i1, b2 = r12 * i1;    // row 1
        float g0 = r20 * i2, g1 = r21 * i2, g2 = r22 * i2;    // row 2

        // rot(0,1) zero b0
        {
            float rr = fmaf(a0, a0, b0 * b0);
            float cc = 1.f, ss = 0.f;
            if (rr > 1e-30f) { float inv = rsqrtf(rr); cc = a0 * inv; ss = b0 * inv; }
            float n0 = fmaf(cc, a0, ss * b0);
            float n1 = fmaf(cc, a1, ss * b1);
            float n2 = fmaf(cc, a2, ss * b2);
            float q1 = fmaf(cc, b1, -ss * a1);
            float q2 = fmaf(cc, b2, -ss * a2);
            a0 = n0; a1 = n1; a2 = n2; b1 = q1; b2 = q2;
        }
        // rot(0,2) zero g0
        {
            float rr = fmaf(a0, a0, g0 * g0);
            float cc = 1.f, ss = 0.f;
            if (rr > 1e-30f) { float inv = rsqrtf(rr); cc = a0 * inv; ss = g0 * inv; }
            float n0 = fmaf(cc, a0, ss * g0);
            float n1 = fmaf(cc, a1, ss * g1);
            float n2 = fmaf(cc, a2, ss * g2);
            float q1 = fmaf(cc, g1, -ss * a1);
            float q2 = fmaf(cc, g2, -ss * a2);
            a0 = n0; a1 = n1; a2 = n2; g1 = q1; g2 = q2;
        }
        // rot(1,2) zero g1 (components 1,2 only)
        {
            float rr = fmaf(b1, b1, g1 * g1);
            float cc = 1.f, ss = 0.f;
            if (rr > 1e-30f) { float inv = rsqrtf(rr); cc = b1 * inv; ss = g1 * inv; }
            float n1 = fmaf(cc, b1, ss * g1);
            float n2 = fmaf(cc, b2, ss * g2);
            float q2 = fmaf(cc, g2, -ss * b2);
            b1 = n1; b2 = n2; g2 = q2;
        }
        // U = [a0 a1 a2; 0 b1 b2; 0 0 g2]

        float cx0 = centers[3 * m + 0];
        float cy0 = centers[3 * m + 1];
        float cz0 = centers[3 * m + 2];
        float k0 = -fmaf(a0, cx0, fmaf(a1, cy0, a2 * cz0));
        float k1 = -fmaf(b1, cy0, b2 * cz0);
        float k2 = -(g2 * cz0);
        float na = log2f(alphas[m]) - 10.0f;   // alpha==0 -> -inf -> 2^e = 0 (correct)

        sg[3 * threadIdx.x + 0] = make_float4(a0, a1, a2, k0);
        sg[3 * threadIdx.x + 1] = make_float4(b1, b2, k1, g2);
        sg[3 * threadIdx.x + 2] = make_float4(k2, na, 0.f, 0.f);
    }
    __syncthreads();

    // ---- main loop: 64 gaussians x 8 points, 10 fma-pipe ops + 1 MUFU per point ----
#pragma unroll 2
    for (int m = 0; m < GCHUNK; m++) {
        float4 w0 = sg[3 * m + 0];
        float4 w1 = sg[3 * m + 1];
        float4 w2 = sg[3 * m + 2];
        float u00 = w0.x, u01 = w0.y, u02 = w0.z, k0 = w0.w;
        float u11 = w1.x, u12 = w1.y, k1 = w1.z, u22 = w1.w;
        float k2 = w2.x, na = w2.y;
#pragma unroll
        for (int j = 0; j < PPT; j++) {
            float t0 = fmaf(u00, px[j], fmaf(u01, py[j], fmaf(u02, pz[j], k0)));
            float t1 = fmaf(u11, py[j], fmaf(u12, pz[j], k1));
            float t2 = fmaf(u22, pz[j], k2);
            // e = na - t0^2 - t1^2 - t2^2 : negation folded into FFMA src modifiers
            float e = fmaf(t0, -t0, fmaf(t1, -t1, fmaf(t2, -t2, na)));
            acc[j] += ex2f(e);
        }
    }

    // ---- write this chunk's partial ----
    float* part = g_partial[blockIdx.y];
#pragma unroll
    for (int j = 0; j < PPT / 2; j++) {
        int idx = base + j * (BLOCK * 2);
        *reinterpret_cast<float2*>(part + idx) = make_float2(acc[2 * j + 0], acc[2 * j + 1]);
    }

    // ---- deterministic last-block combine (ticket monotonic -> replay safe) ----
    __threadfence();
    __syncthreads();
    if (threadIdx.x == 0) s_ticket = atomicAdd(&g_ticket[blockIdx.x], 1u);
    __syncthreads();
    if ((s_ticket & (GSPLIT - 1)) == GSPLIT - 1) {
        __threadfence();
#pragma unroll
        for (int j = 0; j < PPT / 2; j++) {
            int idx = base + j * (BLOCK * 2);
            float s0 = 0.f, s1 = 0.f;
#pragma unroll
            for (int g = 0; g < GSPLIT; g++) {      // fixed order -> bitwise deterministic
                const float2* pp = reinterpret_cast<const float2*>(&g_partial[g][idx]);
                float2 v = __ldcg(pp);
                s0 += v.x; s1 += v.y;
            }
            *reinterpret_cast<float2*>(out + idx) = make_float2(s0, s1);
        }
    }
}

extern "C" void kernel_launch(void* const* d_in, const int* in_sizes, int n_in,
                              void* d_out, int out_size) {
    const float* points  = (const float*)d_in[0];
    const float* centers = (const float*)d_in[1];
    const float* angles  = (const float*)d_in[2];
    const float* scales  = (const float*)d_in[3];
    const float* alphas  = (const float*)d_in[4];
    float* out = (float*)d_out;

    dim3 grid(NPT, GSPLIT);
    eval_kernel<<<grid, BLOCK>>>(points, centers, angles, scales, alphas, out);
}